// round 15
// baseline (speedup 1.0000x reference)
#include <cuda_runtime.h>
#include <cuda_fp16.h>
#include <mma.h>
#include <cstdint>

using namespace nvcuda;

#define NN 8192
#define DD 64
#define GG 2048

// Scratch: fp32 scores (256 MB), half P (128 MB), half X (32 MB),
// hi/lo-split encodings (K=128), norms.
__device__ float g_S[(size_t)NN * NN];
__device__ __half g_Ph[(size_t)NN * NN];
__device__ __half g_Xh[(size_t)NN * GG];
__device__ __half g_EA[(size_t)NN * 128];
__device__ __half g_EB[(size_t)NN * 128];
__device__ float g_norm[NN];

// ---------------------------------------------------------------------------
// helpers
// ---------------------------------------------------------------------------
__device__ __forceinline__ uint32_t smem_u32(const void* p) {
    uint32_t a;
    asm("{ .reg .u64 t; cvta.to.shared.u64 t, %1; cvt.u32.u64 %0, t; }" : "=r"(a) : "l"(p));
    return a;
}
__device__ __forceinline__ void cp_async16(uint32_t s, const void* g) {
    asm volatile("cp.async.cg.shared.global [%0], [%1], 16;" :: "r"(s), "l"(g));
}
__device__ __forceinline__ void cp_commit() {
    asm volatile("cp.async.commit_group;");
}
template <int N>
__device__ __forceinline__ void cp_wait() {
    asm volatile("cp.async.wait_group %0;" :: "n"(N));
}
// Fast distance: sqrt(x) = x * rsqrt(x), single MUFU + FMUL (vs IEEE chain).
// x clamped >= 1e-20 so x=0 can't produce 0*inf; true-zero case (diagonal)
// is overridden exactly in softmax.
__device__ __forceinline__ float fast_sqrt(float x) {
    float t = fmaxf(x, 1e-20f);
    return t * __frsqrt_rn(t);
}

// ---------------------------------------------------------------------------
// K1: row squared norms (fp32, exact)
// ---------------------------------------------------------------------------
__global__ void norms_kernel(const float* __restrict__ enc) {
    int i = blockIdx.x * blockDim.x + threadIdx.x;
    if (i >= NN) return;
    const float4* p = (const float4*)(enc + (size_t)i * DD);
    float s = 0.f;
#pragma unroll
    for (int k = 0; k < DD / 4; k++) {
        float4 v = p[k];
        s += v.x * v.x + v.y * v.y + v.z * v.z + v.w * v.w;
    }
    g_norm[i] = s;
}

// ---------------------------------------------------------------------------
// K1b: asymmetric hi/lo split (K=128):
//   EA = [hi | lo], EB = [hi | hi]  =>  EA·EB = hh + lh
// (drops hl + ll: ~1e-4 score error; diagonal fixed exactly in softmax)
// ---------------------------------------------------------------------------
__global__ void split_enc_kernel(const float* __restrict__ enc) {
    int idx = blockIdx.x * blockDim.x + threadIdx.x;  // over NN*DD
    int row = idx >> 6;
    int col = idx & 63;
    float x = enc[idx];
    __half hi = __float2half_rn(x);
    __half lo = __float2half_rn(x - __half2float(hi));
    size_t b = (size_t)row * 128 + col;
    g_EA[b] = hi; g_EA[b + 64] = lo;
    g_EB[b] = hi; g_EB[b + 64] = hi;
}

// ---------------------------------------------------------------------------
// K2: scores via fp16 wmma over K=128 in 2 pipelined chunks of 64,
// fused transform epilogue: g_S = q[j] - dist(i,j), dist via MUFU rsqrt.
// 2 CTAs/SM (reg-capped). Epilogue norm/qual gathers are float4.
// ---------------------------------------------------------------------------
#define SK_CH 64
#define S_LDM 72                             // halves, padded
#define S_TILE (128 * S_LDM * 2)             // 18432 B
#define S_CHUNK (2 * S_TILE)                 // A+B per chunk = 36864
#define C_LDM 132
#define S_SMEM (2 * S_CHUNK)                 // 73728 (>= 128*132*4 epilogue)

__global__ void __launch_bounds__(256, 2) scores_mm_kernel(const float* __restrict__ qual) {
    extern __shared__ __align__(16) char smem[];
    const uint32_t sbase = smem_u32(smem);
    float* Cs = (float*)smem;
    const int tid = threadIdx.x;
    const int warp = tid >> 5;
    const int warp_m = warp >> 2;   // 0..1
    const int warp_n = warp & 3;    // 0..3
    const int i0 = blockIdx.y * 128;
    const int j0 = blockIdx.x * 128;

    // Issue both chunk loads as separate commit groups (pointer-carried).
    {
        const int row = tid >> 3, cc = tid & 7;
        const __half* pA = g_EA + (size_t)(i0 + row) * 128 + cc * 8;
        const __half* pB = g_EB + (size_t)(j0 + row) * 128 + cc * 8;
        const uint32_t dA = sbase + row * (S_LDM * 2) + cc * 16;
        const uint32_t dB = dA + S_TILE;
#pragma unroll
        for (int s = 0; s < 2; s++) {
            const uint32_t so = s * S_CHUNK;
            const int ko = s * SK_CH;
            cp_async16(dA + so,                  pA + ko);
            cp_async16(dA + so + 32 * S_LDM * 2, pA + ko + (size_t)32 * 128);
            cp_async16(dA + so + 64 * S_LDM * 2, pA + ko + (size_t)64 * 128);
            cp_async16(dA + so + 96 * S_LDM * 2, pA + ko + (size_t)96 * 128);
            cp_async16(dB + so,                  pB + ko);
            cp_async16(dB + so + 32 * S_LDM * 2, pB + ko + (size_t)32 * 128);
            cp_async16(dB + so + 64 * S_LDM * 2, pB + ko + (size_t)64 * 128);
            cp_async16(dB + so + 96 * S_LDM * 2, pB + ko + (size_t)96 * 128);
            cp_commit();
        }
    }

    wmma::fragment<wmma::accumulator, 16, 16, 16, float> cfr[4][2];
#pragma unroll
    for (int i = 0; i < 4; i++)
#pragma unroll
        for (int j = 0; j < 2; j++) wmma::fill_fragment(cfr[i][j], 0.f);

#pragma unroll
    for (int s = 0; s < 2; s++) {
        if (s == 0) cp_wait<1>();
        else cp_wait<0>();
        __syncthreads();
        const __half* As = (const __half*)(smem + s * S_CHUNK);
        const __half* Bs = (const __half*)(smem + s * S_CHUNK + S_TILE);
#pragma unroll
        for (int ks = 0; ks < SK_CH; ks += 16) {
            wmma::fragment<wmma::matrix_a, 16, 16, 16, __half, wmma::row_major> a[4];
            wmma::fragment<wmma::matrix_b, 16, 16, 16, __half, wmma::col_major> b[2];
#pragma unroll
            for (int i = 0; i < 4; i++)
                wmma::load_matrix_sync(a[i], As + (warp_m * 64 + i * 16) * S_LDM + ks, S_LDM);
#pragma unroll
            for (int j = 0; j < 2; j++)
                wmma::load_matrix_sync(b[j], Bs + (warp_n * 32 + j * 16) * S_LDM + ks, S_LDM);
#pragma unroll
            for (int i = 0; i < 4; i++)
#pragma unroll
                for (int j = 0; j < 2; j++)
                    wmma::mma_sync(cfr[i][j], a[i], b[j], cfr[i][j]);
        }
    }

    // Epilogue: frags -> smem -> transform -> fp32 scores to g_S
    __syncthreads();
#pragma unroll
    for (int i = 0; i < 4; i++)
#pragma unroll
        for (int j = 0; j < 2; j++)
            wmma::store_matrix_sync(
                Cs + (warp_m * 64 + i * 16) * C_LDM + warp_n * 32 + j * 16,
                cfr[i][j], C_LDM, wmma::mem_row_major);
    __syncthreads();

    {
        const int r = tid >> 1;             // 0..127
        const int ch = (tid & 1) * 64;      // 0 or 64
        const int i = i0 + r;
        const float nrow = g_norm[i];
        float* orow = g_S + (size_t)i * NN + j0 + ch;
        const float* crow = Cs + r * C_LDM + ch;
        const float4* n4 = (const float4*)(g_norm + j0 + ch);
        const float4* q4 = (const float4*)(qual + j0 + ch);
#pragma unroll
        for (int c4 = 0; c4 < 16; c4++) {
            float4 d = *(const float4*)(crow + c4 * 4);
            float4 nv = n4[c4];
            float4 qv = q4[c4];
            float4 o;
            o.x = qv.x - fast_sqrt(nrow + nv.x - 2.f * d.x);
            o.y = qv.y - fast_sqrt(nrow + nv.y - 2.f * d.y);
            o.z = qv.z - fast_sqrt(nrow + nv.z - 2.f * d.z);
            o.w = qv.w - fast_sqrt(nrow + nv.w - 2.f * d.w);
            *(float4*)(orow + c4 * 4) = o;
        }
    }
}

// ---------------------------------------------------------------------------
// K3: row softmax (exp only), 512 threads / 16 vals for HBM saturation.
// Diagonal forced to qual[row] (true distance 0).
// ---------------------------------------------------------------------------
__global__ void __launch_bounds__(512) softmax_kernel(const float* __restrict__ qual) {
    const int row = blockIdx.x;
    const int tid = threadIdx.x;
    const float* S = g_S + (size_t)row * NN;
    __half* P = g_Ph + (size_t)row * NN;

    float vals[16];
    float m = -1e30f;
#pragma unroll
    for (int k = 0; k < 16; k++) {
        int j = tid + k * 512;
        float sc = S[j];
        vals[k] = (j == row) ? qual[row] : sc;
        m = fmaxf(m, vals[k]);
    }

    __shared__ float red[16];
#pragma unroll
    for (int off = 16; off; off >>= 1) m = fmaxf(m, __shfl_xor_sync(~0u, m, off));
    if ((tid & 31) == 0) red[tid >> 5] = m;
    __syncthreads();
    if (tid < 16) {
        float x = red[tid];
#pragma unroll
        for (int off = 8; off; off >>= 1) x = fmaxf(x, __shfl_xor_sync(0xffffu, x, off));
        if (tid == 0) red[0] = x;
    }
    __syncthreads();
    m = red[0];

    float s = 0.f;
#pragma unroll
    for (int k = 0; k < 16; k++) {
        vals[k] = __expf(vals[k] - m);
        s += vals[k];
    }
    __syncthreads();
#pragma unroll
    for (int off = 16; off; off >>= 1) s += __shfl_xor_sync(~0u, s, off);
    if ((tid & 31) == 0) red[tid >> 5] = s;
    __syncthreads();
    if (tid < 16) {
        float x = red[tid];
#pragma unroll
        for (int off = 8; off; off >>= 1) x += __shfl_xor_sync(0xffffu, x, off);
        if (tid == 0) red[0] = x;
    }
    __syncthreads();
    float inv = 1.f / red[0];
#pragma unroll
    for (int k = 0; k < 16; k++) P[tid + k * 512] = __float2half_rn(vals[k] * inv);
}

// ---------------------------------------------------------------------------
// K3b: convert X (f32) -> half
// ---------------------------------------------------------------------------
__global__ void convx_kernel(const float* __restrict__ X) {
    size_t idx = ((size_t)blockIdx.x * blockDim.x + threadIdx.x) * 4;
    float4 v = *(const float4*)(X + idx);
    __half2* dst = (__half2*)(g_Xh + idx);
    dst[0] = __floats2half2_rn(v.x, v.y);
    dst[1] = __floats2half2_rn(v.z, v.w);
}

// ---------------------------------------------------------------------------
// K4: out = P @ X, fp16 wmma. Tile 128x128, BK=64, 3-stage cp.async,
// single-sync multistage mainloop. 128 threads = 4 warps in 2x2,
// warp tile 64x64, 2 CTAs/SM. (unchanged from round 14)
// ---------------------------------------------------------------------------
#define BM 128
#define BN 128
#define BK 64
#define NSTG 3
#define A_LDM 72                          // halves (64 data + 8 pad)
#define B_LDM 136                         // halves (128 data + 8 pad)
#define A_STG_BYTES (BM * A_LDM * 2)      // 18432
#define B_STG_BYTES (BK * B_LDM * 2)      // 17408
#define STG_BYTES (A_STG_BYTES + B_STG_BYTES)
#define SMEM_GEMM (NSTG * STG_BYTES)      // 107520
#define NCHUNK (NN / BK)                  // 128

__global__ void __launch_bounds__(128, 2) gemm_kernel(float* __restrict__ out) {
    extern __shared__ __align__(16) char smem[];
    const uint32_t sbase = smem_u32(smem);
    const int tid = threadIdx.x;
    const int warp = tid >> 5;      // 0..3
    const int warp_m = warp >> 1;   // 0..1
    const int warp_n = warp & 1;    // 0..1
    const int m0 = blockIdx.y * BM;
    const int n0 = blockIdx.x * BN;

    const int aRow = tid >> 3, aCol = tid & 7;
    const int bRow = tid >> 4, bCol = tid & 15;
    const __half* pA = g_Ph + (size_t)(m0 + aRow) * NN + aCol * 8;
    const __half* pB = g_Xh + (size_t)bRow * GG + n0 + bCol * 8;
    const uint32_t dA0 = sbase + aRow * (A_LDM * 2) + aCol * 16;
    const uint32_t dB0 = sbase + A_STG_BYTES + bRow * (B_LDM * 2) + bCol * 16;

#define ISSUE_CHUNK(stg) do {                                                  \
        const uint32_t _o = (uint32_t)(stg) * STG_BYTES;                       \
        cp_async16(dA0 + _o,                    pA);                           \
        cp_async16(dA0 + _o + 16 * A_LDM * 2,   pA + (size_t)16 * NN);         \
        cp_async16(dA0 + _o + 32 * A_LDM * 2,   pA + (size_t)32 * NN);         \
        cp_async16(dA0 + _o + 48 * A_LDM * 2,   pA + (size_t)48 * NN);         \
        cp_async16(dA0 + _o + 64 * A_LDM * 2,   pA + (size_t)64 * NN);         \
        cp_async16(dA0 + _o + 80 * A_LDM * 2,   pA + (size_t)80 * NN);         \
        cp_async16(dA0 + _o + 96 * A_LDM * 2,   pA + (size_t)96 * NN);         \
        cp_async16(dA0 + _o + 112 * A_LDM * 2,  pA + (size_t)112 * NN);        \
        cp_async16(dB0 + _o,                    pB);                           \
        cp_async16(dB0 + _o + 8 * B_LDM * 2,    pB + (size_t)8 * GG);          \
        cp_async16(dB0 + _o + 16 * B_LDM * 2,   pB + (size_t)16 * GG);         \
        cp_async16(dB0 + _o + 24 * B_LDM * 2,   pB + (size_t)24 * GG);         \
        cp_async16(dB0 + _o + 32 * B_LDM * 2,   pB + (size_t)32 * GG);         \
        cp_async16(dB0 + _o + 40 * B_LDM * 2,   pB + (size_t)40 * GG);         \
        cp_async16(dB0 + _o + 48 * B_LDM * 2,   pB + (size_t)48 * GG);         \
        cp_async16(dB0 + _o + 56 * B_LDM * 2,   pB + (size_t)56 * GG);         \
        cp_commit();                                                           \
        pA += BK;                                                              \
        pB += (size_t)BK * GG;                                                 \
    } while (0)

    wmma::fragment<wmma::accumulator, 16, 16, 16, float> cfr[4][4];
#pragma unroll
    for (int i = 0; i < 4; i++)
#pragma unroll
        for (int j = 0; j < 4; j++) wmma::fill_fragment(cfr[i][j], 0.f);

    ISSUE_CHUNK(0);
    ISSUE_CHUNK(1);

    for (int c = 0; c < NCHUNK; c++) {
        const int st = c % NSTG;
        const __half* Ah = (const __half*)(smem + st * STG_BYTES);
        const __half* Bh = (const __half*)(smem + st * STG_BYTES + A_STG_BYTES);

        if (c + 1 < NCHUNK) cp_wait<NSTG - 2>(); else cp_wait<0>();
        __syncthreads();
        if (c + NSTG - 1 < NCHUNK) ISSUE_CHUNK((c + NSTG - 1) % NSTG);

#pragma unroll
        for (int ks = 0; ks < BK; ks += 16) {
            wmma::fragment<wmma::matrix_a, 16, 16, 16, __half, wmma::row_major> a[4];
#pragma unroll
            for (int i = 0; i < 4; i++)
                wmma::load_matrix_sync(a[i], Ah + (warp_m * 64 + i * 16) * A_LDM + ks, A_LDM);
#pragma unroll
            for (int j = 0; j < 4; j++) {
                wmma::fragment<wmma::matrix_b, 16, 16, 16, __half, wmma::row_major> b;
                wmma::load_matrix_sync(b, Bh + ks * B_LDM + warp_n * 64 + j * 16, B_LDM);
#pragma unroll
                for (int i = 0; i < 4; i++)
                    wmma::mma_sync(cfr[i][j], a[i], b, cfr[i][j]);
            }
        }
    }
#undef ISSUE_CHUNK

#pragma unroll
    for (int i = 0; i < 4; i++)
#pragma unroll
        for (int j = 0; j < 4; j++)
            wmma::store_matrix_sync(
                out + (size_t)(m0 + warp_m * 64 + i * 16) * GG + n0 + warp_n * 64 + j * 16,
                cfr[i][j], GG, wmma::mem_row_major);
}

// ---------------------------------------------------------------------------
extern "C" void kernel_launch(void* const* d_in, const int* in_sizes, int n_in,
                              void* d_out, int out_size) {
    const float* expr = nullptr;  // N*G
    const float* enc = nullptr;   // N*D
    const float* qual = nullptr;  // N
    for (int i = 0; i < n_in; i++) {
        if (in_sizes[i] == NN * GG) expr = (const float*)d_in[i];
        else if (in_sizes[i] == NN * DD) enc = (const float*)d_in[i];
        else if (in_sizes[i] == NN) qual = (const float*)d_in[i];
    }
    float* out = (float*)d_out;

    cudaFuncSetAttribute(scores_mm_kernel, cudaFuncAttributeMaxDynamicSharedMemorySize,
                         S_SMEM);
    cudaFuncSetAttribute(gemm_kernel, cudaFuncAttributeMaxDynamicSharedMemorySize,
                         SMEM_GEMM);

    norms_kernel<<<NN / 256, 256>>>(enc);
    split_enc_kernel<<<(NN * DD) / 256, 256>>>(enc);
    dim3 g2(NN / 128, NN / 128);
    scores_mm_kernel<<<g2, 256, S_SMEM>>>(qual);
    softmax_kernel<<<NN, 512>>>(qual);
    convx_kernel<<<(NN * GG) / (256 * 4), 256>>>(expr);
    dim3 g4(GG / BN, NN / BM);
    gemm_kernel<<<g4, 128, SMEM_GEMM>>>(out);
}

// round 17
// speedup vs baseline: 1.0428x; 1.0428x over previous
#include <cuda_runtime.h>
#include <cuda_fp16.h>
#include <mma.h>
#include <cstdint>

using namespace nvcuda;

#define NN 8192
#define DD 64
#define GG 2048

// Scratch: half unnormalized P (128 MB), half X (32 MB),
// hi/lo-split encodings (K=128), norms, row sums.
__device__ __half g_Ph[(size_t)NN * NN];
__device__ __half g_Xh[(size_t)NN * GG];
__device__ __half g_EA[(size_t)NN * 128];
__device__ __half g_EB[(size_t)NN * 128];
__device__ float g_norm[NN];
__device__ float g_rowsum[NN];

// ---------------------------------------------------------------------------
// helpers
// ---------------------------------------------------------------------------
__device__ __forceinline__ uint32_t smem_u32(const void* p) {
    uint32_t a;
    asm("{ .reg .u64 t; cvta.to.shared.u64 t, %1; cvt.u32.u64 %0, t; }" : "=r"(a) : "l"(p));
    return a;
}
__device__ __forceinline__ void cp_async16(uint32_t s, const void* g) {
    asm volatile("cp.async.cg.shared.global [%0], [%1], 16;" :: "r"(s), "l"(g));
}
__device__ __forceinline__ void cp_commit() {
    asm volatile("cp.async.commit_group;");
}
template <int N>
__device__ __forceinline__ void cp_wait() {
    asm volatile("cp.async.wait_group %0;" :: "n"(N));
}
// sqrt(x) = x * rsqrt(x): 1 MUFU + 1 FMUL; clamp avoids 0*inf at x=0.
__device__ __forceinline__ float fast_sqrt(float x) {
    float t = fmaxf(x, 1e-20f);
    return t * __frsqrt_rn(t);
}

// ---------------------------------------------------------------------------
// K1: row squared norms (fp32, exact) + zero the row-sum accumulators
// ---------------------------------------------------------------------------
__global__ void norms_kernel(const float* __restrict__ enc) {
    int i = blockIdx.x * blockDim.x + threadIdx.x;
    if (i >= NN) return;
    const float4* p = (const float4*)(enc + (size_t)i * DD);
    float s = 0.f;
#pragma unroll
    for (int k = 0; k < DD / 4; k++) {
        float4 v = p[k];
        s += v.x * v.x + v.y * v.y + v.z * v.z + v.w * v.w;
    }
    g_norm[i] = s;
    g_rowsum[i] = 0.f;
}

// ---------------------------------------------------------------------------
// K1b: asymmetric hi/lo split (K=128):
//   EA = [hi | lo], EB = [hi | hi]  =>  EA·EB = hh + lh
// ---------------------------------------------------------------------------
__global__ void split_enc_kernel(const float* __restrict__ enc) {
    int idx = blockIdx.x * blockDim.x + threadIdx.x;  // over NN*DD
    int row = idx >> 6;
    int col = idx & 63;
    float x = enc[idx];
    __half hi = __float2half_rn(x);
    __half lo = __float2half_rn(x - __half2float(hi));
    size_t b = (size_t)row * 128 + col;
    g_EA[b] = hi; g_EA[b + 64] = lo;
    g_EB[b] = hi; g_EB[b + 64] = hi;
}

// ---------------------------------------------------------------------------
// K2: fused scores + exp. dot via fp16 wmma over K=128 (2 pipelined chunks),
// epilogue writes P_unnorm[i,j] = exp(q[j] - dist(i,j) - q[i]) as HALF
// (diagonal forced to exactly 1.0 = exp(0); q[i] is the row max since
// off-diagonal dist ~ 11 >> q spread, and softmax is shift-invariant),
// and atomically accumulates row sums. 2 CTAs/SM.
// ---------------------------------------------------------------------------
#define SK_CH 64
#define S_LDM 72                             // halves, padded
#define S_TILE (128 * S_LDM * 2)             // 18432 B
#define S_CHUNK (2 * S_TILE)                 // A+B per chunk = 36864
#define C_LDM 132
#define S_SMEM (2 * S_CHUNK)                 // 73728 (>= 128*132*4 epilogue)

__global__ void __launch_bounds__(256, 2) scores_mm_kernel(const float* __restrict__ qual) {
    extern __shared__ __align__(16) char smem[];
    const uint32_t sbase = smem_u32(smem);
    float* Cs = (float*)smem;
    const int tid = threadIdx.x;
    const int warp = tid >> 5;
    const int warp_m = warp >> 2;   // 0..1
    const int warp_n = warp & 3;    // 0..3
    const int i0 = blockIdx.y * 128;
    const int j0 = blockIdx.x * 128;

    // Issue both chunk loads as separate commit groups (pointer-carried).
    {
        const int row = tid >> 3, cc = tid & 7;
        const __half* pA = g_EA + (size_t)(i0 + row) * 128 + cc * 8;
        const __half* pB = g_EB + (size_t)(j0 + row) * 128 + cc * 8;
        const uint32_t dA = sbase + row * (S_LDM * 2) + cc * 16;
        const uint32_t dB = dA + S_TILE;
#pragma unroll
        for (int s = 0; s < 2; s++) {
            const uint32_t so = s * S_CHUNK;
            const int ko = s * SK_CH;
            cp_async16(dA + so,                  pA + ko);
            cp_async16(dA + so + 32 * S_LDM * 2, pA + ko + (size_t)32 * 128);
            cp_async16(dA + so + 64 * S_LDM * 2, pA + ko + (size_t)64 * 128);
            cp_async16(dA + so + 96 * S_LDM * 2, pA + ko + (size_t)96 * 128);
            cp_async16(dB + so,                  pB + ko);
            cp_async16(dB + so + 32 * S_LDM * 2, pB + ko + (size_t)32 * 128);
            cp_async16(dB + so + 64 * S_LDM * 2, pB + ko + (size_t)64 * 128);
            cp_async16(dB + so + 96 * S_LDM * 2, pB + ko + (size_t)96 * 128);
            cp_commit();
        }
    }

    wmma::fragment<wmma::accumulator, 16, 16, 16, float> cfr[4][2];
#pragma unroll
    for (int i = 0; i < 4; i++)
#pragma unroll
        for (int j = 0; j < 2; j++) wmma::fill_fragment(cfr[i][j], 0.f);

#pragma unroll
    for (int s = 0; s < 2; s++) {
        if (s == 0) cp_wait<1>();
        else cp_wait<0>();
        __syncthreads();
        const __half* As = (const __half*)(smem + s * S_CHUNK);
        const __half* Bs = (const __half*)(smem + s * S_CHUNK + S_TILE);
#pragma unroll
        for (int ks = 0; ks < SK_CH; ks += 16) {
            wmma::fragment<wmma::matrix_a, 16, 16, 16, __half, wmma::row_major> a[4];
            wmma::fragment<wmma::matrix_b, 16, 16, 16, __half, wmma::col_major> b[2];
#pragma unroll
            for (int i = 0; i < 4; i++)
                wmma::load_matrix_sync(a[i], As + (warp_m * 64 + i * 16) * S_LDM + ks, S_LDM);
#pragma unroll
            for (int j = 0; j < 2; j++)
                wmma::load_matrix_sync(b[j], Bs + (warp_n * 32 + j * 16) * S_LDM + ks, S_LDM);
#pragma unroll
            for (int i = 0; i < 4; i++)
#pragma unroll
                for (int j = 0; j < 2; j++)
                    wmma::mma_sync(cfr[i][j], a[i], b[j], cfr[i][j]);
        }
    }

    // Epilogue: frags -> smem -> exp-transform -> half P_unnorm + row sums
    __syncthreads();
#pragma unroll
    for (int i = 0; i < 4; i++)
#pragma unroll
        for (int j = 0; j < 2; j++)
            wmma::store_matrix_sync(
                Cs + (warp_m * 64 + i * 16) * C_LDM + warp_n * 32 + j * 16,
                cfr[i][j], C_LDM, wmma::mem_row_major);
    __syncthreads();

    {
        const int r = tid >> 1;             // 0..127
        const int ch = (tid & 1) * 64;      // 0 or 64
        const int i = i0 + r;
        const float nrow = g_norm[i];
        const float qrow = qual[i];
        __half* orow = g_Ph + (size_t)i * NN + j0 + ch;
        const float* crow = Cs + r * C_LDM + ch;
        const float4* n4 = (const float4*)(g_norm + j0 + ch);
        const float4* q4 = (const float4*)(qual + j0 + ch);
        const bool diagblk = (i0 == j0);
        float psum = 0.f;
#pragma unroll
        for (int c4 = 0; c4 < 16; c4++) {
            float4 d = *(const float4*)(crow + c4 * 4);
            float4 nv = n4[c4];
            float4 qv = q4[c4];
            float4 o;
            o.x = __expf(qv.x - fast_sqrt(nrow + nv.x - 2.f * d.x) - qrow);
            o.y = __expf(qv.y - fast_sqrt(nrow + nv.y - 2.f * d.y) - qrow);
            o.z = __expf(qv.z - fast_sqrt(nrow + nv.z - 2.f * d.z) - qrow);
            o.w = __expf(qv.w - fast_sqrt(nrow + nv.w - 2.f * d.w) - qrow);
            if (diagblk) {
                int jj = j0 + ch + c4 * 4;
                if (jj + 0 == i) o.x = 1.f;
                if (jj + 1 == i) o.y = 1.f;
                if (jj + 2 == i) o.z = 1.f;
                if (jj + 3 == i) o.w = 1.f;
            }
            psum += o.x + o.y + o.z + o.w;
            __half2 h0 = __floats2half2_rn(o.x, o.y);
            __half2 h1 = __floats2half2_rn(o.z, o.w);
            *(uint2*)(orow + c4 * 4) = make_uint2(
                *(const uint32_t*)&h0, *(const uint32_t*)&h1);
        }
        // Combine the two half-row partials (threads tid, tid^1 share row r).
        float other = __shfl_xor_sync(~0u, psum, 1);
        if ((tid & 1) == 0) atomicAdd(g_rowsum + i, psum + other);
    }
}

// ---------------------------------------------------------------------------
// K3b: convert X (f32) -> half
// ---------------------------------------------------------------------------
__global__ void convx_kernel(const float* __restrict__ X) {
    size_t idx = ((size_t)blockIdx.x * blockDim.x + threadIdx.x) * 4;
    float4 v = *(const float4*)(X + idx);
    __half2* dst = (__half2*)(g_Xh + idx);
    dst[0] = __floats2half2_rn(v.x, v.y);
    dst[1] = __floats2half2_rn(v.z, v.w);
}

// ---------------------------------------------------------------------------
// K4: out = P_unnorm @ X, fp16 wmma. Tile 128x128, BK=64, 3-stage cp.async,
// single-sync multistage mainloop, 4 warps 2x2, warp tile 64x64, 2 CTAs/SM.
// ---------------------------------------------------------------------------
#define BM 128
#define BN 128
#define BK 64
#define NSTG 3
#define A_LDM 72                          // halves (64 data + 8 pad)
#define B_LDM 136                         // halves (128 data + 8 pad)
#define A_STG_BYTES (BM * A_LDM * 2)      // 18432
#define B_STG_BYTES (BK * B_LDM * 2)      // 17408
#define STG_BYTES (A_STG_BYTES + B_STG_BYTES)
#define SMEM_GEMM (NSTG * STG_BYTES)      // 107520
#define NCHUNK (NN / BK)                  // 128

__global__ void __launch_bounds__(128, 2) gemm_kernel(float* __restrict__ out) {
    extern __shared__ __align__(16) char smem[];
    const uint32_t sbase = smem_u32(smem);
    const int tid = threadIdx.x;
    const int warp = tid >> 5;      // 0..3
    const int warp_m = warp >> 1;   // 0..1
    const int warp_n = warp & 1;    // 0..1
    const int m0 = blockIdx.y * BM;
    const int n0 = blockIdx.x * BN;

    const int aRow = tid >> 3, aCol = tid & 7;
    const int bRow = tid >> 4, bCol = tid & 15;
    const __half* pA = g_Ph + (size_t)(m0 + aRow) * NN + aCol * 8;
    const __half* pB = g_Xh + (size_t)bRow * GG + n0 + bCol * 8;
    const uint32_t dA0 = sbase + aRow * (A_LDM * 2) + aCol * 16;
    const uint32_t dB0 = sbase + A_STG_BYTES + bRow * (B_LDM * 2) + bCol * 16;

#define ISSUE_CHUNK(stg) do {                                                  \
        const uint32_t _o = (uint32_t)(stg) * STG_BYTES;                       \
        cp_async16(dA0 + _o,                    pA);                           \
        cp_async16(dA0 + _o + 16 * A_LDM * 2,   pA + (size_t)16 * NN);         \
        cp_async16(dA0 + _o + 32 * A_LDM * 2,   pA + (size_t)32 * NN);         \
        cp_async16(dA0 + _o + 48 * A_LDM * 2,   pA + (size_t)48 * NN);         \
        cp_async16(dA0 + _o + 64 * A_LDM * 2,   pA + (size_t)64 * NN);         \
        cp_async16(dA0 + _o + 80 * A_LDM * 2,   pA + (size_t)80 * NN);         \
        cp_async16(dA0 + _o + 96 * A_LDM * 2,   pA + (size_t)96 * NN);         \
        cp_async16(dA0 + _o + 112 * A_LDM * 2,  pA + (size_t)112 * NN);        \
        cp_async16(dB0 + _o,                    pB);                           \
        cp_async16(dB0 + _o + 8 * B_LDM * 2,    pB + (size_t)8 * GG);          \
        cp_async16(dB0 + _o + 16 * B_LDM * 2,   pB + (size_t)16 * GG);         \
        cp_async16(dB0 + _o + 24 * B_LDM * 2,   pB + (size_t)24 * GG);         \
        cp_async16(dB0 + _o + 32 * B_LDM * 2,   pB + (size_t)32 * GG);         \
        cp_async16(dB0 + _o + 40 * B_LDM * 2,   pB + (size_t)40 * GG);         \
        cp_async16(dB0 + _o + 48 * B_LDM * 2,   pB + (size_t)48 * GG);         \
        cp_async16(dB0 + _o + 56 * B_LDM * 2,   pB + (size_t)56 * GG);         \
        cp_commit();                                                           \
        pA += BK;                                                              \
        pB += (size_t)BK * GG;                                                 \
    } while (0)

    wmma::fragment<wmma::accumulator, 16, 16, 16, float> cfr[4][4];
#pragma unroll
    for (int i = 0; i < 4; i++)
#pragma unroll
        for (int j = 0; j < 4; j++) wmma::fill_fragment(cfr[i][j], 0.f);

    ISSUE_CHUNK(0);
    ISSUE_CHUNK(1);

    for (int c = 0; c < NCHUNK; c++) {
        const int st = c % NSTG;
        const __half* Ah = (const __half*)(smem + st * STG_BYTES);
        const __half* Bh = (const __half*)(smem + st * STG_BYTES + A_STG_BYTES);

        if (c + 1 < NCHUNK) cp_wait<NSTG - 2>(); else cp_wait<0>();
        __syncthreads();
        if (c + NSTG - 1 < NCHUNK) ISSUE_CHUNK((c + NSTG - 1) % NSTG);

#pragma unroll
        for (int ks = 0; ks < BK; ks += 16) {
            wmma::fragment<wmma::matrix_a, 16, 16, 16, __half, wmma::row_major> a[4];
#pragma unroll
            for (int i = 0; i < 4; i++)
                wmma::load_matrix_sync(a[i], Ah + (warp_m * 64 + i * 16) * A_LDM + ks, A_LDM);
#pragma unroll
            for (int j = 0; j < 4; j++) {
                wmma::fragment<wmma::matrix_b, 16, 16, 16, __half, wmma::row_major> b;
                wmma::load_matrix_sync(b, Bh + ks * B_LDM + warp_n * 64 + j * 16, B_LDM);
#pragma unroll
                for (int i = 0; i < 4; i++)
                    wmma::mma_sync(cfr[i][j], a[i], b, cfr[i][j]);
            }
        }
    }
#undef ISSUE_CHUNK

#pragma unroll
    for (int i = 0; i < 4; i++)
#pragma unroll
        for (int j = 0; j < 4; j++)
            wmma::store_matrix_sync(
                out + (size_t)(m0 + warp_m * 64 + i * 16) * GG + n0 + warp_n * 64 + j * 16,
                cfr[i][j], GG, wmma::mem_row_major);
}

// ---------------------------------------------------------------------------
// K5: normalize output rows by the softmax denominators.
// One block per row; 512 threads x float4 covers G=2048 exactly.
// ---------------------------------------------------------------------------
__global__ void __launch_bounds__(512) scale_kernel(float* __restrict__ out) {
    const int row = blockIdx.x;
    const float inv = 1.f / g_rowsum[row];
    float4* p = (float4*)(out + (size_t)row * GG) + threadIdx.x;
    float4 v = *p;
    v.x *= inv; v.y *= inv; v.z *= inv; v.w *= inv;
    *p = v;
}

// ---------------------------------------------------------------------------
extern "C" void kernel_launch(void* const* d_in, const int* in_sizes, int n_in,
                              void* d_out, int out_size) {
    const float* expr = nullptr;  // N*G
    const float* enc = nullptr;   // N*D
    const float* qual = nullptr;  // N
    for (int i = 0; i < n_in; i++) {
        if (in_sizes[i] == NN * GG) expr = (const float*)d_in[i];
        else if (in_sizes[i] == NN * DD) enc = (const float*)d_in[i];
        else if (in_sizes[i] == NN) qual = (const float*)d_in[i];
    }
    float* out = (float*)d_out;

    cudaFuncSetAttribute(scores_mm_kernel, cudaFuncAttributeMaxDynamicSharedMemorySize,
                         S_SMEM);
    cudaFuncSetAttribute(gemm_kernel, cudaFuncAttributeMaxDynamicSharedMemorySize,
                         SMEM_GEMM);

    norms_kernel<<<NN / 256, 256>>>(enc);
    split_enc_kernel<<<(NN * DD) / 256, 256>>>(enc);
    dim3 g2(NN / 128, NN / 128);
    scores_mm_kernel<<<g2, 256, S_SMEM>>>(qual);
    convx_kernel<<<(NN * GG) / (256 * 4), 256>>>(expr);
    dim3 g4(GG / BN, NN / BM);
    gemm_kernel<<<g4, 128, SMEM_GEMM>>>(out);
    scale_kernel<<<NN, 512>>>(out);
}